// round 10
// baseline (speedup 1.0000x reference)
#include <cuda_runtime.h>
#include <math.h>

#define NB 4096
#define NL 20

// ------- scratch (static device globals; 16B-aligned for float4 access) -----
static __device__ __align__(16) float g_h1[NB*32*14*14];
static __device__ __align__(16) float g_h2[NB*32*7*7];
static __device__ __align__(16) float g_h3[NB*64*4*4];
static __device__ __align__(16) float g_hf[NB*256];
static __device__ __align__(16) float g_z [NB*NL];
static __device__ __align__(16) float g_f2[NB*256];
static __device__ __align__(16) float g_f3[NB*1024];
static __device__ __align__(16) float g_e1[NB*32*7*7];
static __device__ __align__(16) float g_e2[NB*32*14*14];

__device__ __forceinline__ float f4g(float4 v, int e){
    return e==0 ? v.x : (e==1 ? v.y : (e==2 ? v.z : v.w));
}

// ---------------- conv1: [B,1,28,28] -> [B,32,14,14], k4 s2 p1, relu -------
// thread = (n, oy, co); warp = 32 co of same (n,oy) => input loads uniform
__global__ void k_conv1(const float* __restrict__ x, const float* __restrict__ w,
                        const float* __restrict__ bias){
    int idx = blockIdx.x*blockDim.x + threadIdx.x;
    if (idx >= NB*14*32) return;
    int co = idx & 31;
    int t  = idx >> 5;
    int oy = t % 14;
    int n  = t / 14;

    float acc[14];
    #pragma unroll
    for (int i=0;i<14;i++) acc[i]=0.f;

    float wr[16];
    const float4* w4 = (const float4*)(w + co*16);
    #pragma unroll
    for (int i=0;i<4;i++){ float4 v=w4[i]; wr[4*i]=v.x; wr[4*i+1]=v.y; wr[4*i+2]=v.z; wr[4*i+3]=v.w; }

    const float* xin = x + n*784;
    #pragma unroll
    for (int ky=0;ky<4;ky++){
        int iy = 2*oy - 1 + ky;
        if (iy < 0 || iy >= 28) continue;
        float row[28];
        const float4* r4 = (const float4*)(xin + iy*28);
        #pragma unroll
        for (int i=0;i<7;i++){ float4 v=r4[i]; row[4*i]=v.x; row[4*i+1]=v.y; row[4*i+2]=v.z; row[4*i+3]=v.w; }
        #pragma unroll
        for (int ox=0;ox<14;ox++){
            #pragma unroll
            for (int kx=0;kx<4;kx++){
                int ix = 2*ox - 1 + kx;
                if (ix < 0 || ix >= 28) continue;
                acc[ox] += row[ix]*wr[ky*4+kx];
            }
        }
    }
    float b0 = bias[co];
    float* out = g_h1 + ((size_t)(n*32+co)*14 + oy)*14;
    #pragma unroll
    for (int ox=0;ox<14;ox++) out[ox] = fmaxf(acc[ox]+b0, 0.f);
}

// ---------------- conv2: [B,32,14,14] -> [B,32,7,7], k4 s2 p1, relu --------
// thread = (n, co); input-centric scatter, acc[49] in regs
__global__ void __launch_bounds__(128) k_conv2(const float* __restrict__ w,
                                               const float* __restrict__ bias){
    int idx = blockIdx.x*blockDim.x + threadIdx.x;
    if (idx >= NB*32) return;
    int co = idx & 31;
    int n  = idx >> 5;

    float acc[49];
    #pragma unroll
    for (int i=0;i<49;i++) acc[i]=0.f;

    const float4* in4 = (const float4*)(g_h1 + (size_t)n*32*196);
    for (int ci=0; ci<32; ci++){
        float wr[16];
        const float4* w4 = (const float4*)(w + ((size_t)co*32+ci)*16);
        #pragma unroll
        for (int i=0;i<4;i++){ float4 v=w4[i]; wr[4*i]=v.x; wr[4*i+1]=v.y; wr[4*i+2]=v.z; wr[4*i+3]=v.w; }
        #pragma unroll
        for (int j=0;j<49;j++){
            float4 v4 = in4[ci*49 + j];
            #pragma unroll
            for (int e=0;e<4;e++){
                int pos = j*4+e;
                int iy = pos/14, ix = pos%14;
                int oyH=(iy+1)>>1, kyA=(iy+1)&1;
                int oxH=(ix+1)>>1, kxA=(ix+1)&1;
                float v = f4g(v4,e);
                #pragma unroll
                for (int dy=0;dy<2;dy++){
                    int oy=oyH-dy, ky=kyA+2*dy;
                    if (oy<0 || oy>=7) continue;
                    #pragma unroll
                    for (int dx=0;dx<2;dx++){
                        int ox=oxH-dx, kx=kxA+2*dx;
                        if (ox<0 || ox>=7) continue;
                        acc[oy*7+ox] += v*wr[ky*4+kx];
                    }
                }
            }
        }
    }
    float b0 = bias[co];
    float* out = g_h2 + (size_t)(n*32+co)*49;
    #pragma unroll
    for (int i=0;i<49;i++) out[i] = fmaxf(acc[i]+b0, 0.f);
}

// ---------------- conv3: [B,32,7,7] -> [B,64,4,4], k3 s2 p1, relu ----------
// thread = (n, co); input scatter grouped by 4 ci for float4-aligned loads
__global__ void __launch_bounds__(128) k_conv3(const float* __restrict__ w,
                                               const float* __restrict__ bias){
    int idx = blockIdx.x*blockDim.x + threadIdx.x;
    if (idx >= NB*64) return;
    int co = idx & 63;
    int n  = idx >> 6;

    float acc[16];
    #pragma unroll
    for (int i=0;i<16;i++) acc[i]=0.f;

    const float4* in4 = (const float4*)(g_h2 + (size_t)n*32*49);
    for (int cg=0; cg<8; cg++){
        float wl[36]; // 4 ci x 9 weights, aligned: co*288 + cg*36 (both /4)
        const float4* w4 = (const float4*)(w + (size_t)co*288 + cg*36);
        #pragma unroll
        for (int i=0;i<9;i++){ float4 v=w4[i]; wl[4*i]=v.x; wl[4*i+1]=v.y; wl[4*i+2]=v.z; wl[4*i+3]=v.w; }
        #pragma unroll
        for (int j=0;j<49;j++){
            float4 v4 = in4[cg*49 + j];
            #pragma unroll
            for (int e=0;e<4;e++){
                int pos = j*4+e;
                int cl = pos/49, rem = pos%49;
                int iy = rem/7, ix = rem%7;
                int oyA=(iy+1)>>1, kyA=(iy+1)&1;
                int oxA=(ix+1)>>1, kxA=(ix+1)&1;
                float v = f4g(v4,e);
                #pragma unroll
                for (int dy=0;dy<2;dy++){
                    int oy=oyA-dy, ky=kyA+2*dy;
                    if (ky>2 || oy<0 || oy>=4) continue;
                    #pragma unroll
                    for (int dx=0;dx<2;dx++){
                        int ox=oxA-dx, kx=kxA+2*dx;
                        if (kx>2 || ox<0 || ox>=4) continue;
                        acc[oy*4+ox] += v*wl[cl*9 + ky*3 + kx];
                    }
                }
            }
        }
    }
    float b0 = bias[co];
    float* out = g_h3 + (size_t)(n*64+co)*16;
    #pragma unroll
    for (int i=0;i<16;i++) out[i] = fmaxf(acc[i]+b0, 0.f);
}

// ---------------- fc1: [B,1024] -> [B,256], relu ---------------------------
// block = 256 threads (one output each) x 16 batch rows; k tiled by 256
__global__ void k_fc1(const float* __restrict__ w, const float* __restrict__ bias){
    __shared__ float smem[16*256];
    int o  = threadIdx.x;
    int n0 = blockIdx.x*16;
    float acc[16];
    #pragma unroll
    for (int r=0;r<16;r++) acc[r]=0.f;

    for (int kt=0; kt<4; kt++){
        __syncthreads();
        #pragma unroll
        for (int i=0;i<4;i++){
            int li = threadIdx.x + i*256;   // float4 index 0..1023
            int r = li >> 6, c = li & 63;
            ((float4*)smem)[li] = *(const float4*)(g_h3 + (size_t)(n0+r)*1024 + kt*256 + c*4);
        }
        __syncthreads();
        const float4* wrow = (const float4*)(w + (size_t)o*1024 + kt*256);
        #pragma unroll 8
        for (int k=0;k<64;k++){
            float4 wv = wrow[k];
            #pragma unroll
            for (int r=0;r<16;r++){
                float4 iv = ((const float4*)smem)[r*64+k];
                acc[r] += wv.x*iv.x + wv.y*iv.y + wv.z*iv.z + wv.w*iv.w;
            }
        }
    }
    float b0 = bias[o];
    #pragma unroll
    for (int r=0;r<16;r++)
        g_hf[(size_t)(n0+r)*256 + o] = fmaxf(acc[r]+b0, 0.f);
}

// -------- mu / logvar heads + 100-step recursion + reparameterize ----------
__global__ void k_latent(const float* __restrict__ wmu, const float* __restrict__ bmu,
                         const float* __restrict__ wls, const float* __restrict__ bls,
                         const float* __restrict__ eps, float* __restrict__ out){
    int idx = blockIdx.x*blockDim.x + threadIdx.x;
    if (idx >= NB*NL) return;
    int l = idx % NL;
    int n = idx / NL;

    const float4* h4 = (const float4*)(g_hf + (size_t)n*256);
    const float4* a4 = (const float4*)(wmu + (size_t)l*256);
    const float4* c4 = (const float4*)(wls + (size_t)l*256);
    float mu = 0.f, ls = 0.f;
    #pragma unroll 8
    for (int k=0;k<64;k++){
        float4 h=h4[k], a=a4[k], c=c4[k];
        mu += h.x*a.x + h.y*a.y + h.z*a.z + h.w*a.w;
        ls += h.x*c.x + h.y*c.y + h.z*c.z + h.w*c.w;
    }
    mu += bmu[l];
    ls += bls[l];

    // outputs 2 & 3: mu, logvar (pre-recursion)
    out[(size_t)NB*784 + idx]          = mu;
    out[(size_t)NB*784 + NB*NL + idx]  = ls;

    float m = mu, s = ls;
    #pragma unroll 4
    for (int t=0;t<100;t++){
        m = fmaf(0.1f, m, m);
        s = fmaf(0.05f, expf(s) - 1.0f, s);
    }
    g_z[idx] = fmaf(eps[idx], expf(0.5f*s), m);
}

// ---------------- fc2: [B,20] -> [B,256], relu -----------------------------
__global__ void k_fc2(const float* __restrict__ w, const float* __restrict__ bias){
    int idx = blockIdx.x*blockDim.x + threadIdx.x;
    if (idx >= NB*256) return;
    int o = idx & 255;
    int n = idx >> 8;
    const float* z  = g_z + (size_t)n*NL;
    const float* wr = w + (size_t)o*NL;
    float acc = bias[o];
    #pragma unroll
    for (int k=0;k<NL;k++) acc += z[k]*wr[k];
    g_f2[idx] = fmaxf(acc, 0.f);
}

// ---------------- fc3: [B,256] -> [B,1024], relu ---------------------------
__global__ void k_fc3(const float* __restrict__ w, const float* __restrict__ bias){
    __shared__ float smem[16*256];
    int o  = blockIdx.y*256 + threadIdx.x;
    int n0 = blockIdx.x*16;
    #pragma unroll
    for (int i=0;i<4;i++){
        int li = threadIdx.x + i*256;
        ((float4*)smem)[li] = ((const float4*)(g_f2 + (size_t)n0*256))[li];
    }
    __syncthreads();
    float acc[16];
    #pragma unroll
    for (int r=0;r<16;r++) acc[r]=0.f;
    const float4* wrow = (const float4*)(w + (size_t)o*256);
    #pragma unroll 8
    for (int k=0;k<64;k++){
        float4 wv = wrow[k];
        #pragma unroll
        for (int r=0;r<16;r++){
            float4 iv = ((const float4*)smem)[r*64+k];
            acc[r] += wv.x*iv.x + wv.y*iv.y + wv.z*iv.z + wv.w*iv.w;
        }
    }
    float b0 = bias[o];
    #pragma unroll
    for (int r=0;r<16;r++)
        g_f3[(size_t)(n0+r)*1024 + o] = fmaxf(acc[r]+b0, 0.f);
}

// ------- deconv1: [B,64,4,4] -> [B,32,7,7], k3 s2 p1, relu -----------------
// ConvTranspose scatter: out[2*iy-1+ky][2*ix-1+kx] += in[iy][ix]*w[ci][co][ky][kx]
__global__ void __launch_bounds__(128) k_dec1(const float* __restrict__ w,
                                              const float* __restrict__ bias){
    int idx = blockIdx.x*blockDim.x + threadIdx.x;
    if (idx >= NB*32) return;
    int co = idx & 31;
    int n  = idx >> 5;

    float acc[49];
    #pragma unroll
    for (int i=0;i<49;i++) acc[i]=0.f;

    const float4* in4 = (const float4*)(g_f3 + (size_t)n*1024);
    for (int ci=0; ci<64; ci++){
        float wl[9];
        const float* wb = w + ((size_t)ci*32 + co)*9;
        #pragma unroll
        for (int i=0;i<9;i++) wl[i] = wb[i];
        float4 p0=in4[ci*4+0], p1=in4[ci*4+1], p2=in4[ci*4+2], p3=in4[ci*4+3];
        float vv[16] = {p0.x,p0.y,p0.z,p0.w, p1.x,p1.y,p1.z,p1.w,
                        p2.x,p2.y,p2.z,p2.w, p3.x,p3.y,p3.z,p3.w};
        #pragma unroll
        for (int pos=0; pos<16; pos++){
            int iy = pos>>2, ix = pos&3;
            float v = vv[pos];
            #pragma unroll
            for (int ky=0;ky<3;ky++){
                int oy = 2*iy - 1 + ky;
                if (oy<0 || oy>=7) continue;
                #pragma unroll
                for (int kx=0;kx<3;kx++){
                    int ox = 2*ix - 1 + kx;
                    if (ox<0 || ox>=7) continue;
                    acc[oy*7+ox] += v*wl[ky*3+kx];
                }
            }
        }
    }
    float b0 = bias[co];
    float* out = g_e1 + (size_t)(n*32+co)*49;
    #pragma unroll
    for (int i=0;i<49;i++) out[i] = fmaxf(acc[i]+b0, 0.f);
}

// ------- deconv2: [B,32,7,7] -> [B,32,14,14], k4 s2 p1, relu ---------------
// parity-class decomposition (A,Bc = output row/col parity), templated so all
// accumulator indices fold to constants. Body unchanged from the 4-launch
// version; now dispatched by blockIdx.y in ONE launch (saves 3 launch gaps).
template<int A, int Bc>
__device__ __forceinline__ void dec2_body(const float* __restrict__ w,
                                          const float* __restrict__ bias){
    int idx = blockIdx.x*blockDim.x + threadIdx.x;
    if (idx >= NB*32) return;
    int co = idx & 31;
    int n  = idx >> 5;

    float acc[49];
    #pragma unroll
    for (int i=0;i<49;i++) acc[i]=0.f;

    const float4* in4 = (const float4*)(g_e1 + (size_t)n*1568);
    for (int cg=0; cg<8; cg++){
        float wl[4][4]; // [ci_local][dy*2+dx]
        #pragma unroll
        for (int c=0;c<4;c++){
            int ci = cg*4 + c;
            const float* wb = w + ((size_t)ci*32 + co)*16;
            #pragma unroll
            for (int dy=0;dy<2;dy++){
                int ky = (A==0) ? (1+2*dy) : (2-2*dy);
                #pragma unroll
                for (int dx=0;dx<2;dx++){
                    int kx = (Bc==0) ? (1+2*dx) : (2-2*dx);
                    wl[c][dy*2+dx] = wb[ky*4+kx];
                }
            }
        }
        #pragma unroll
        for (int j=0;j<49;j++){
            float4 v4 = in4[cg*49 + j];
            #pragma unroll
            for (int e=0;e<4;e++){
                int pos = j*4+e;
                int c = pos/49, rem = pos%49;
                int iy = rem/7, ix = rem%7;
                float v = f4g(v4,e);
                #pragma unroll
                for (int dy=0;dy<2;dy++){
                    int m = iy + (dy==0 ? 0 : (A==0 ? 1 : -1));
                    if (m<0 || m>=7) continue;
                    #pragma unroll
                    for (int dx=0;dx<2;dx++){
                        int nn = ix + (dx==0 ? 0 : (Bc==0 ? 1 : -1));
                        if (nn<0 || nn>=7) continue;
                        acc[m*7+nn] += v*wl[c][dy*2+dx];
                    }
                }
            }
        }
    }
    float b0 = bias[co];
    float* o = g_e2 + (size_t)(n*32+co)*196;
    #pragma unroll
    for (int m=0;m<7;m++)
        #pragma unroll
        for (int nn=0;nn<7;nn++)
            o[(2*m+A)*14 + 2*nn+Bc] = fmaxf(acc[m*7+nn]+b0, 0.f);
}

__global__ void __launch_bounds__(128) k_dec2_all(const float* __restrict__ w,
                                                  const float* __restrict__ bias){
    switch (blockIdx.y){
        case 0: dec2_body<0,0>(w, bias); break;
        case 1: dec2_body<0,1>(w, bias); break;
        case 2: dec2_body<1,0>(w, bias); break;
        default: dec2_body<1,1>(w, bias); break;
    }
}

// ------- deconv3 + sigmoid: [B,32,14,14] -> [B,1,28,28] --------------------
// thread = (n, m): owns output rows 2m and 2m+1 (56 accumulators)
__global__ void __launch_bounds__(128) k_dec3(const float* __restrict__ w,
                                              const float* __restrict__ bias,
                                              float* __restrict__ out){
    int idx = blockIdx.x*blockDim.x + threadIdx.x;
    if (idx >= NB*14) return;
    int m = idx % 14;
    int n = idx / 14;

    float acc0[28], acc1[28];
    #pragma unroll
    for (int i=0;i<28;i++){ acc0[i]=0.f; acc1[i]=0.f; }

    const float* in = g_e2 + (size_t)n*32*196;
    for (int ci=0; ci<32; ci++){
        float wl[16];
        const float4* w4 = (const float4*)(w + (size_t)ci*16);
        #pragma unroll
        for (int i=0;i<4;i++){ float4 v=w4[i]; wl[4*i]=v.x; wl[4*i+1]=v.y; wl[4*i+2]=v.z; wl[4*i+3]=v.w; }
        const float* inc = in + ci*196;
        #pragma unroll
        for (int dr=0; dr<3; dr++){
            int iy = m - 1 + dr;
            if (iy < 0 || iy >= 14) continue;
            float row[14];
            #pragma unroll
            for (int i=0;i<14;i++) row[i] = inc[iy*14+i];
            const int ky0 = 3 - 2*dr;  // weight row feeding output row 2m   (valid 0..3)
            const int ky1 = 4 - 2*dr;  // weight row feeding output row 2m+1 (valid 0..3)
            #pragma unroll
            for (int ix=0; ix<14; ix++){
                float v = row[ix];
                #pragma unroll
                for (int kx=0; kx<4; kx++){
                    int ox = 2*ix - 1 + kx;
                    if (ox<0 || ox>=28) continue;
                    if (ky0>=0 && ky0<4) acc0[ox] += v*wl[ky0*4+kx];
                    if (ky1>=0 && ky1<4) acc1[ox] += v*wl[ky1*4+kx];
                }
            }
        }
    }
    float b0 = bias[0];
    float* o0 = out + (size_t)n*784 + (2*m  )*28;
    float* o1 = out + (size_t)n*784 + (2*m+1)*28;
    #pragma unroll
    for (int ox=0; ox<28; ox++){
        float v0 = acc0[ox]+b0, v1 = acc1[ox]+b0;
        o0[ox] = 1.f/(1.f+expf(-v0));
        o1[ox] = 1.f/(1.f+expf(-v1));
    }
}

// ---------------------------------------------------------------------------
extern "C" void kernel_launch(void* const* d_in, const int* in_sizes, int n_in,
                              void* d_out, int out_size){
    const float* x     = (const float*)d_in[0];
    const float* eps   = (const float*)d_in[1];
    const float* w_c1  = (const float*)d_in[2];  const float* b_c1 = (const float*)d_in[3];
    const float* w_c2  = (const float*)d_in[4];  const float* b_c2 = (const float*)d_in[5];
    const float* w_c3  = (const float*)d_in[6];  const float* b_c3 = (const float*)d_in[7];
    const float* w_fc1 = (const float*)d_in[8];  const float* b_fc1= (const float*)d_in[9];
    const float* w_mu  = (const float*)d_in[10]; const float* b_mu = (const float*)d_in[11];
    const float* w_ls  = (const float*)d_in[12]; const float* b_ls = (const float*)d_in[13];
    const float* w_fc2 = (const float*)d_in[14]; const float* b_fc2= (const float*)d_in[15];
    const float* w_fc3 = (const float*)d_in[16]; const float* b_fc3= (const float*)d_in[17];
    const float* w_d1  = (const float*)d_in[18]; const float* b_d1 = (const float*)d_in[19];
    const float* w_d2  = (const float*)d_in[20]; const float* b_d2 = (const float*)d_in[21];
    const float* w_d3  = (const float*)d_in[22]; const float* b_d3 = (const float*)d_in[23];
    float* out = (float*)d_out;

    k_conv1<<<(NB*14*32)/256, 256>>>(x, w_c1, b_c1);
    k_conv2<<<(NB*32)/128, 128>>>(w_c2, b_c2);
    k_conv3<<<(NB*64)/128, 128>>>(w_c3, b_c3);
    k_fc1<<<NB/16, 256>>>(w_fc1, b_fc1);
    k_latent<<<(NB*NL)/256, 256>>>(w_mu, b_mu, w_ls, b_ls, eps, out);
    k_fc2<<<(NB*256)/256, 256>>>(w_fc2, b_fc2);
    { dim3 g(NB/16, 4); k_fc3<<<g, 256>>>(w_fc3, b_fc3); }
    k_dec1<<<(NB*32)/128, 128>>>(w_d1, b_d1);
    { dim3 g((NB*32)/128, 4); k_dec2_all<<<g, 128>>>(w_d2, b_d2); }
    k_dec3<<<(NB*14+127)/128, 128>>>(w_d3, b_d3, out);
}